// round 14
// baseline (speedup 1.0000x reference)
#include <cuda_runtime.h>

#define NROWS 65536
#define FDIM  64
#define EDIM  16
#define NH1   8
#define NH2   4
#define BN_EPS 1e-5f
#define NCTA  128
#define NTHR  512
#define ROWS_CTA 512              /* rows per CTA == NTHR: 1 row/thread */
#define ROWS_A (NROWS / NCTA)     /* 512 rows per CTA in phase A */
#define TP 20                     /* padded floats per row per quarter (16 used) */
#define BUF_FLOATS (ROWS_CTA * TP)            /* 10240 floats per array per buffer */
#define BUF_STRIDE (2 * BUF_FLOATS)           /* Xa + Xc per buffer */
#define DYN_BYTES (2 * BUF_STRIDE * 4)        /* 163840 bytes */

typedef unsigned long long u64;

// ---- device scratch ----
__device__ float g_part[NCTA * FDIM];
__device__ float g_hstat[2 * NH1];
__device__ unsigned g_cnt0 = 0, g_cnt1 = 0;
__device__ unsigned g_gen0 = 0, g_gen1 = 0;

// ---- f32x2 helpers ----
__device__ __forceinline__ u64 pk2(float x, float y) {
    u64 r; asm("mov.b64 %0, {%1,%2};" : "=l"(r) : "f"(x), "f"(y)); return r;
}
__device__ __forceinline__ u64 fma2(u64 a, u64 b, u64 c) {
    u64 d; asm("fma.rn.f32x2 %0, %1, %2, %3;" : "=l"(d) : "l"(a), "l"(b), "l"(c)); return d;
}
__device__ __forceinline__ u64 mul2(u64 a, u64 b) {
    u64 d; asm("mul.rn.f32x2 %0, %1, %2;" : "=l"(d) : "l"(a), "l"(b)); return d;
}
__device__ __forceinline__ float2 upk(u64 v) {
    float2 r; asm("mov.b64 {%0,%1}, %2;" : "=f"(r.x), "=f"(r.y) : "l"(v)); return r;
}

// ---- grid barrier (all NCTA CTAs resident; NCTA <= 148, 1 CTA/SM) ----
__device__ __forceinline__ void grid_bar(unsigned* cnt, unsigned* gen) {
    __syncthreads();
    if (threadIdx.x == 0) {
        volatile unsigned* vg = (volatile unsigned*)gen;
        unsigned my = *vg;
        __threadfence();
        if (atomicAdd(cnt, 1) == NCTA - 1) {
            *cnt = 0;
            __threadfence();
            *vg = my + 1;
        } else {
            while (*vg == my) __nanosleep(64);
        }
    }
    __syncthreads();
    __threadfence();
}

__device__ __forceinline__ float ftanh(float x) {
    float xx = fminf(fmaxf(x, -15.f), 15.f);
    float t = __expf(2.f * xx);
    return __fdividef(t - 1.f, t + 1.f);
}

extern __shared__ float dynsm[];

// issue cp.async for quarter q into buffer (q&1) — incremental addressing
__device__ __forceinline__ void issue_quarter(const float* Xa, const float* Xc,
                                              int cta, int q, int tid)
{
    int row = tid >> 2, c = tid & 3;      // 128 rows covered per iteration
    const float4* A = (const float4*)Xa + (size_t)cta * (ROWS_CTA * 16) + q * 4
                      + row * 16 + c;
    const float4* C = (const float4*)Xc + (size_t)cta * (ROWS_CTA * 16) + q * 4
                      + row * 16 + c;
    unsigned dA = (unsigned)__cvta_generic_to_shared(
                      dynsm + (q & 1) * BUF_STRIDE + row * TP + c * 4);
    unsigned dC = dA + BUF_FLOATS * 4;
    #pragma unroll
    for (int it = 0; it < 4; it++) {
        asm volatile("cp.async.cg.shared.global [%0], [%1], 16;" :: "r"(dA), "l"(A));
        asm volatile("cp.async.cg.shared.global [%0], [%1], 16;" :: "r"(dC), "l"(C));
        A += 128 * 16; C += 128 * 16;              // advance 128 rows
        dA += 128 * TP * 4; dC += 128 * TP * 4;
    }
    asm volatile("cp.async.commit_group;");
}

__global__ void __launch_bounds__(NTHR) k_all(
    const float* __restrict__ Xa, const float* __restrict__ Xc,
    const float* __restrict__ w1, const float* __restrict__ b1,
    const float* __restrict__ w2, const float* __restrict__ b2,
    const float* __restrict__ W1, const float* __restrict__ B1,
    const float* __restrict__ W2, const float* __restrict__ B2,
    const float* __restrict__ L1w, const float* __restrict__ L1b,
    const float* __restrict__ gam, const float* __restrict__ bet,
    const float* __restrict__ L2w, const float* __restrict__ L2b,
    float* __restrict__ out)
{
    __shared__ ulonglong2 sS[FDIM * 12];   // per f: U[4 ull2], B1[4], B2[4]
    __shared__ float      sMhF[FDIM * 24]; // per f: P[8],Q[8],R[8]
    __shared__ u64        sCq[FDIM * 6];   // per f: (m0,m1)(m2,2m3)(2m4,2m5)(w1,b1)(k,0) pre-scaled
    __shared__ float4     spA[NTHR];
    __shared__ float      sRed[8 * FDIM];
    __shared__ float      sXc[FDIM];
    __shared__ float      sStat[16];
    __shared__ float      sFin[32];

    int tid = threadIdx.x;
    int cta = blockIdx.x;
    const float4* Xc4 = (const float4*)Xc;

    // ---- prologue: quarters 0 and 1 in flight (hidden behind phases A/B) ----
    issue_quarter(Xa, Xc, cta, 0, tid);
    issue_quarter(Xa, Xc, cta, 1, tid);

    // ================= Phase A: Xc column partial sums =================
    {
        int f4 = tid & 15, rg = tid >> 4;          // 16 quads x 32 row-groups
        float4 acc = make_float4(0.f, 0.f, 0.f, 0.f);
        size_t r = (size_t)cta * ROWS_A + rg;
        #pragma unroll 8
        for (int it = 0; it < ROWS_A / 32; it++, r += 32) {
            float4 v = Xc4[r * 16 + f4];
            acc.x += v.x; acc.y += v.y; acc.z += v.z; acc.w += v.w;
        }
        spA[tid] = acc;
        __syncthreads();
        if (tid < 16) {
            float4 t = make_float4(0.f, 0.f, 0.f, 0.f);
            #pragma unroll
            for (int g = 0; g < 32; g++) {
                float4 v = spA[g * 16 + tid];
                t.x += v.x; t.y += v.y; t.z += v.z; t.w += v.w;
            }
            ((float4*)g_part)[cta * 16 + tid] = t;
        }
        if (cta == 0 && tid < 16) g_hstat[tid] = 0.f;
    }
    grid_bar(&g_cnt0, &g_gen0);

    // ================= Phase B: constants (each CTA redundantly) =================
    {
        int col = tid & 63, grp = tid >> 6;        // 8 groups of 64
        float acc = 0.f;
        #pragma unroll 8
        for (int p = grp; p < NCTA; p += 8)
            acc += __ldcg(&g_part[p * FDIM + col]);
        sRed[grp * FDIM + col] = acc;
    }
    if (tid < FDIM * 4) {
        // fill sS: FDIM*4 = 256 float4 slots
        float4* sSf = (float4*)sS;
        int idx = tid;
        int f = idx >> 2, j = idx & 3;
        float4 w1v = ((const float4*)W1)[idx];
        float4 w2v = ((const float4*)W2)[idx];
        sSf[f * 12 + j] = make_float4(w1v.x + w2v.x, w1v.y + w2v.y,
                                      w1v.z + w2v.z, w1v.w + w2v.w);
        sSf[f * 12 + 4 + j] = ((const float4*)B1)[idx];
        sSf[f * 12 + 8 + j] = ((const float4*)B2)[idx];
    }
    if (tid < 16) sStat[tid] = 0.f;
    __syncthreads();
    if (tid < FDIM) {
        float s = 0.f;
        #pragma unroll
        for (int g = 0; g < 8; g++) s += sRed[g * FDIM + tid];
        sXc[tid] = s;
    }
    __syncthreads();
    if (tid < FDIM) {
        int f = tid;
        const float* Uf  = (const float*)&sS[f * 12];
        const float* B1f = Uf + 16;
        const float* B2f = Uf + 32;
        float m0 = 0, m1 = 0, m2 = 0, m3 = 0, m4 = 0, m5 = 0;
        #pragma unroll
        for (int e = 0; e < EDIM; e++) {
            float u = Uf[e], x = B1f[e], y = B2f[e];
            m0 += u * u; m1 += x * x; m2 += y * y;
            m3 += u * x; m4 += u * y; m5 += x * y;
        }
        float xcm = sXc[f] * (1.0f / NROWS);
        float kf = w2[f] * xcm + b2[f];
        const float sF = 1.0f / FDIM;
        const float sQ = 1.0f / 32.0f;
        sCq[f * 6 + 0] = pk2(m0 * sQ, m1 * sQ);
        sCq[f * 6 + 1] = pk2(m2 * sQ, 2.f * m3 * sQ);
        sCq[f * 6 + 2] = pk2(2.f * m4 * sQ, 2.f * m5 * sQ);
        sCq[f * 6 + 3] = pk2(w1[f] * sF, b1[f] * sF);
        sCq[f * 6 + 4] = pk2(kf * sF, 0.f);
        sCq[f * 6 + 5] = 0ull;
    }
    {
        // FDIM*NH1 = 512 == NTHR: exactly one (f,j) per thread
        int f = tid >> 3, j = tid & 7;
        const float* lr  = L1w + j * (FDIM * EDIM) + f * EDIM;
        const float* Uf  = (const float*)&sS[f * 12];
        const float* B1f = Uf + 16;
        const float* B2f = Uf + 32;
        float P = 0, Q = 0, R = 0;
        #pragma unroll
        for (int e = 0; e < EDIM; e++) {
            float l = lr[e];
            P += Uf[e] * l; Q += B1f[e] * l; R += B2f[e] * l;
        }
        sMhF[f * 24 + j]      = P;
        sMhF[f * 24 + 8 + j]  = Q;
        sMhF[f * 24 + 16 + j] = R;
    }
    __syncthreads();

    // ================= Phase C: 4-quarter pipelined pass, 1 row/thread =================
    u64 sE[8], hv[4], ffv = 0ull, qv = 0ull;
    #pragma unroll
    for (int g = 0; g < 8; g++) sE[g] = 0ull;
    #pragma unroll
    for (int j = 0; j < 4; j++) hv[j] = 0ull;

    #pragma unroll 1
    for (int k = 0; k < 4; k++) {
        if (k < 3) asm volatile("cp.async.wait_group 1;" ::: "memory");
        else       asm volatile("cp.async.wait_group 0;" ::: "memory");
        __syncthreads();

        const float* bufA = dynsm + (k & 1) * BUF_STRIDE + tid * TP;

        #pragma unroll
        for (int l = 0; l < 4; l++) {
            float4 xa = *(const float4*)(bufA + l * 4);
            float4 xc = *(const float4*)(bufA + l * 4 + BUF_FLOATS);
            #pragma unroll
            for (int u = 0; u < 4; u++) {
                int f = k * 16 + l * 4 + u;
                float a = ((const float*)&xa)[u];
                float c = ((const float*)&xc)[u];
                float ac = a * c;
                u64 aa = pk2(a, a), cc = pk2(c, c), acac = pk2(ac, ac);

                // ---- ff + quad (lane-paired) ----
                {
                    const ulonglong2* cqp = (const ulonglong2*)&sCq[f * 6];
                    ulonglong2 cq0 = cqp[0];       // (m0,m1) (m2,2m3)
                    ulonglong2 cq1 = cqp[1];       // (2m4,2m5) (w1,b1)
                    u64 kq = sCq[f * 6 + 4];       // (k,0)
                    u64 P1 = pk2(ac, c);
                    qv = fma2(mul2(P1, P1), cq0.x, qv);
                    qv = fma2(mul2(pk2(a, ac), pk2(a, c)), cq0.y, qv);
                    qv = fma2(mul2(acac, pk2(a, 1.0f)), cq1.x, qv);
                    ffv = fma2(P1, cq1.y, ffv);
                    ffv = fma2(aa, kq, ffv);       // lane1 adds a*0
                }

                // ---- s[e] matvec: 12 LDS.128 ----
                const ulonglong2* sp = &sS[f * 12];
                #pragma unroll
                for (int g = 0; g < 4; g++) {
                    ulonglong2 uu  = sp[g];
                    ulonglong2 bb1 = sp[4 + g];
                    ulonglong2 bb2 = sp[8 + g];
                    sE[2*g]   = fma2(uu.x,  acac, sE[2*g]);
                    sE[2*g+1] = fma2(uu.y,  acac, sE[2*g+1]);
                    sE[2*g]   = fma2(bb1.x, cc,   sE[2*g]);
                    sE[2*g+1] = fma2(bb1.y, cc,   sE[2*g+1]);
                    sE[2*g]   = fma2(bb2.x, aa,   sE[2*g]);
                    sE[2*g+1] = fma2(bb2.y, aa,   sE[2*g+1]);
                }
                // ---- h matvec: 6 LDS.128 ----
                {
                    const ulonglong2* mh = (const ulonglong2*)&sMhF[f * 24];
                    ulonglong2 P0 = mh[0], Pq = mh[1];
                    hv[0] = fma2(P0.x, acac, hv[0]);
                    hv[1] = fma2(P0.y, acac, hv[1]);
                    hv[2] = fma2(Pq.x, acac, hv[2]);
                    hv[3] = fma2(Pq.y, acac, hv[3]);
                    ulonglong2 Q0 = mh[2], Qq = mh[3];
                    hv[0] = fma2(Q0.x, cc, hv[0]);
                    hv[1] = fma2(Q0.y, cc, hv[1]);
                    hv[2] = fma2(Qq.x, cc, hv[2]);
                    hv[3] = fma2(Qq.y, cc, hv[3]);
                    ulonglong2 R0 = mh[4], Rq = mh[5];
                    hv[0] = fma2(R0.x, aa, hv[0]);
                    hv[1] = fma2(R0.y, aa, hv[1]);
                    hv[2] = fma2(Rq.x, aa, hv[2]);
                    hv[3] = fma2(Rq.y, aa, hv[3]);
                }
            }
        }
        __syncthreads();              // buffer (k&1) fully consumed
        if (k < 2) issue_quarter(Xa, Xc, cta, k + 2, tid);
    }

    // ---- finalize fm parts ----
    float outv;
    {
        u64 ssv = 0ull;
        #pragma unroll
        for (int e = 0; e < 8; e++) ssv = fma2(sE[e], sE[e], ssv);
        float2 sv = upk(ssv);
        float2 fp = upk(ffv);
        float2 qq = upk(qv);
        outv = (fp.x + fp.y) + (sv.x + sv.y) * (1.0f / 32.0f) - (qq.x + qq.y);
    }

    // ---- h with lin1_b ----
    float hvf[8];
    {
        float4 lb0 = __ldg((const float4*)L1b);
        float4 lb1 = __ldg((const float4*)L1b + 1);
        float lb[8] = {lb0.x, lb0.y, lb0.z, lb0.w, lb1.x, lb1.y, lb1.z, lb1.w};
        #pragma unroll
        for (int j = 0; j < 4; j++) {
            float2 t = upk(hv[j]);
            hvf[2*j]   = t.x + lb[2*j];
            hvf[2*j+1] = t.y + lb[2*j+1];
        }
    }

    // ---- BN stats ----
    {
        float st[16];
        #pragma unroll
        for (int j = 0; j < NH1; j++) {
            st[j]     = hvf[j];
            st[8 + j] = hvf[j] * hvf[j];
        }
        #pragma unroll
        for (int off = 16; off; off >>= 1) {
            #pragma unroll
            for (int j = 0; j < 16; j++)
                st[j] += __shfl_xor_sync(0xffffffffu, st[j], off);
        }
        if ((tid & 31) == 0) {
            #pragma unroll
            for (int j = 0; j < 16; j++) atomicAdd(&sStat[j], st[j]);
        }
        __syncthreads();
        if (tid < 16) atomicAdd(&g_hstat[tid], sStat[tid]);
    }
    grid_bar(&g_cnt1, &g_gen1);

    // ================= Phase D: BN finalize + tanh + lin2 + store =================
    if (tid < NH1) {
        float sh = __ldcg(&g_hstat[tid]);
        float sq = __ldcg(&g_hstat[NH1 + tid]);
        float mu  = sh * (1.0f / NROWS);
        float var = sq * (1.0f / NROWS) - mu * mu;
        float rs  = rsqrtf(var + BN_EPS);
        float al  = gam[tid] * rs;
        sFin[tid] = al;
        sFin[8 + tid] = bet[tid] - mu * al;
        float v = 0.f;
        #pragma unroll
        for (int j = 0; j < NH2; j++) v += L2w[j * NH1 + tid];
        sFin[16 + tid] = v * (1.0f / NH2);
    }
    if (tid == 0) {
        float cb = 0.f;
        #pragma unroll
        for (int j = 0; j < NH2; j++) cb += L2b[j];
        sFin[24] = cb * (1.0f / NH2);
    }
    __syncthreads();

    {
        float acc = sFin[24];
        #pragma unroll
        for (int j = 0; j < NH1; j++)
            acc += sFin[16 + j] * ftanh(sFin[j] * hvf[j] + sFin[8 + j]);
        out[cta * ROWS_CTA + tid] = outv + acc;
    }
}

extern "C" void kernel_launch(void* const* d_in, const int* in_sizes, int n_in,
                              void* d_out, int out_size)
{
    const float* Xa  = (const float*)d_in[0];
    const float* Xc  = (const float*)d_in[1];
    const float* w1  = (const float*)d_in[2];
    const float* b1  = (const float*)d_in[3];
    const float* w2  = (const float*)d_in[4];
    const float* b2  = (const float*)d_in[5];
    const float* W1  = (const float*)d_in[6];
    const float* B1  = (const float*)d_in[7];
    const float* W2  = (const float*)d_in[8];
    const float* B2  = (const float*)d_in[9];
    const float* L1w = (const float*)d_in[10];
    const float* L1b = (const float*)d_in[11];
    const float* g1  = (const float*)d_in[12];
    const float* be1 = (const float*)d_in[13];
    const float* L2w = (const float*)d_in[14];
    const float* L2b = (const float*)d_in[15];
    float* out = (float*)d_out;

    cudaFuncSetAttribute(k_all, cudaFuncAttributeMaxDynamicSharedMemorySize, DYN_BYTES);
    k_all<<<NCTA, NTHR, DYN_BYTES>>>(Xa, Xc, w1, b1, w2, b2, W1, B1, W2, B2,
                                     L1w, L1b, g1, be1, L2w, L2b, out);
}

// round 15
// speedup vs baseline: 1.2292x; 1.2292x over previous
#include <cuda_runtime.h>

#define NROWS 65536
#define FDIM  64
#define EDIM  16
#define NH1   8
#define NH2   4
#define BN_EPS 1e-5f
#define NCTA  128
#define NTHR  256
#define ROWS_CTA 512              /* rows per CTA */
#define ROWS_A (NROWS / NCTA)     /* 512 rows per CTA in phase A */
#define QBUF_BYTES (ROWS_CTA * 128)           /* 65536: 512 rows x (64B Xa | 64B Xc) */
#define DYN_BYTES (2 * QBUF_BYTES)            /* 131072 */

typedef unsigned long long u64;

// ---- device scratch ----
__device__ float g_part[NCTA * FDIM];
__device__ float g_hstat[2 * NH1];
__device__ unsigned g_cnt0 = 0, g_cnt1 = 0;
__device__ unsigned g_gen0 = 0, g_gen1 = 0;

// ---- f32x2 helpers ----
__device__ __forceinline__ u64 pk2(float x, float y) {
    u64 r; asm("mov.b64 %0, {%1,%2};" : "=l"(r) : "f"(x), "f"(y)); return r;
}
__device__ __forceinline__ u64 fma2(u64 a, u64 b, u64 c) {
    u64 d; asm("fma.rn.f32x2 %0, %1, %2, %3;" : "=l"(d) : "l"(a), "l"(b), "l"(c)); return d;
}
__device__ __forceinline__ u64 mul2(u64 a, u64 b) {
    u64 d; asm("mul.rn.f32x2 %0, %1, %2;" : "=l"(d) : "l"(a), "l"(b)); return d;
}
__device__ __forceinline__ float2 upk(u64 v) {
    float2 r; asm("mov.b64 {%0,%1}, %2;" : "=f"(r.x), "=f"(r.y) : "l"(v)); return r;
}

// ---- grid barrier (all NCTA CTAs resident; NCTA <= 148, 1 CTA/SM) ----
__device__ __forceinline__ void grid_bar(unsigned* cnt, unsigned* gen) {
    __syncthreads();
    if (threadIdx.x == 0) {
        volatile unsigned* vg = (volatile unsigned*)gen;
        unsigned my = *vg;
        __threadfence();
        if (atomicAdd(cnt, 1) == NCTA - 1) {
            *cnt = 0;
            __threadfence();
            *vg = my + 1;
        } else {
            while (*vg == my) __nanosleep(64);
        }
    }
    __syncthreads();
    __threadfence();
}

__device__ __forceinline__ float ftanh(float x) {
    float xx = fminf(fmaxf(x, -15.f), 15.f);
    float t = __expf(2.f * xx);
    return __fdividef(t - 1.f, t + 1.f);
}

extern __shared__ float dynsm[];

// issue cp.async for quarter q into buffer (q&1), SW128-swizzled interleaved rows
__device__ __forceinline__ void issue_quarter(const float* Xa, const float* Xc,
                                              int cta, int q, int tid)
{
    int r0 = tid >> 3, c = tid & 7;       // 32 rows x 8 chunks per iteration
    size_t gb = (size_t)cta * ROWS_CTA;
    const float4* src = (c < 4)
        ? (const float4*)Xa + (gb + r0) * 16 + q * 4 + c
        : (const float4*)Xc + (gb + r0) * 16 + q * 4 + (c - 4);
    unsigned off = (unsigned)(r0 * 128 + c * 16);
    off ^= (off >> 3) & 0x70;             // SW128 swizzle (invariant under row += 32)
    unsigned dst = (unsigned)__cvta_generic_to_shared(dynsm)
                   + (q & 1) * QBUF_BYTES + off;
    #pragma unroll 4
    for (int it = 0; it < 16; it++) {
        asm volatile("cp.async.cg.shared.global [%0], [%1], 16;" :: "r"(dst), "l"(src));
        src += 32 * 16;                   // advance 32 rows in GMEM
        dst += 32 * 128;                  // advance 32 rows in SMEM
    }
    asm volatile("cp.async.commit_group;");
}

__global__ void __launch_bounds__(NTHR) k_all(
    const float* __restrict__ Xa, const float* __restrict__ Xc,
    const float* __restrict__ w1, const float* __restrict__ b1,
    const float* __restrict__ w2, const float* __restrict__ b2,
    const float* __restrict__ W1, const float* __restrict__ B1,
    const float* __restrict__ W2, const float* __restrict__ B2,
    const float* __restrict__ L1w, const float* __restrict__ L1b,
    const float* __restrict__ gam, const float* __restrict__ bet,
    const float* __restrict__ L2w, const float* __restrict__ L2b,
    float* __restrict__ out)
{
    __shared__ ulonglong2 sS[FDIM * 12];   // per f: U[4 ull2], B1[4], B2[4]
    __shared__ float      sMhF[FDIM * 24]; // per f: P[8],Q[8],R[8]
    __shared__ u64        sCq[FDIM * 6];   // per f: (m0,m1)(m2,2m3)(2m4,2m5)(w1,b1)(k,0) pre-scaled
    __shared__ float4     spA[NTHR];
    __shared__ float      sRed[4 * FDIM];
    __shared__ float      sXc[FDIM];
    __shared__ float      sStat[16];
    __shared__ float      sFin[32];

    int tid = threadIdx.x;
    int cta = blockIdx.x;
    const float4* Xc4 = (const float4*)Xc;

    // ---- prologue: quarters 0 and 1 in flight (hidden behind phases A/B) ----
    issue_quarter(Xa, Xc, cta, 0, tid);
    issue_quarter(Xa, Xc, cta, 1, tid);

    // ================= Phase A: Xc column partial sums =================
    {
        int f4 = tid & 15, rg = tid >> 4;          // 16 quads x 16 row-groups
        float4 acc = make_float4(0.f, 0.f, 0.f, 0.f);
        size_t r = (size_t)cta * ROWS_A + rg;
        #pragma unroll 4
        for (int it = 0; it < ROWS_A / 16; it++, r += 16) {
            float4 v = Xc4[r * 16 + f4];
            acc.x += v.x; acc.y += v.y; acc.z += v.z; acc.w += v.w;
        }
        spA[tid] = acc;
        __syncthreads();
        if (tid < 16) {
            float4 t = make_float4(0.f, 0.f, 0.f, 0.f);
            #pragma unroll
            for (int g = 0; g < 16; g++) {
                float4 v = spA[g * 16 + tid];
                t.x += v.x; t.y += v.y; t.z += v.z; t.w += v.w;
            }
            ((float4*)g_part)[cta * 16 + tid] = t;
        }
        if (cta == 0 && tid < 16) g_hstat[tid] = 0.f;
    }
    grid_bar(&g_cnt0, &g_gen0);

    // ================= Phase B: constants (each CTA redundantly) =================
    {
        int col = tid & 63, grp = tid >> 6;        // 4 groups of 64
        float acc = 0.f;
        #pragma unroll 8
        for (int p = grp; p < NCTA; p += 4)
            acc += __ldcg(&g_part[p * FDIM + col]);
        sRed[grp * FDIM + col] = acc;
    }
    {
        // fill sS: FDIM*4 = 256 float4 slots, one per thread
        float4* sSf = (float4*)sS;
        int f = tid >> 2, j = tid & 3;
        float4 w1v = ((const float4*)W1)[tid];
        float4 w2v = ((const float4*)W2)[tid];
        sSf[f * 12 + j] = make_float4(w1v.x + w2v.x, w1v.y + w2v.y,
                                      w1v.z + w2v.z, w1v.w + w2v.w);
        sSf[f * 12 + 4 + j] = ((const float4*)B1)[tid];
        sSf[f * 12 + 8 + j] = ((const float4*)B2)[tid];
    }
    if (tid < 16) sStat[tid] = 0.f;
    __syncthreads();
    if (tid < FDIM)
        sXc[tid] = sRed[tid] + sRed[FDIM + tid] + sRed[2 * FDIM + tid] + sRed[3 * FDIM + tid];
    __syncthreads();
    if (tid < FDIM) {
        int f = tid;
        const float* Uf  = (const float*)&sS[f * 12];
        const float* B1f = Uf + 16;
        const float* B2f = Uf + 32;
        float m0 = 0, m1 = 0, m2 = 0, m3 = 0, m4 = 0, m5 = 0;
        #pragma unroll
        for (int e = 0; e < EDIM; e++) {
            float u = Uf[e], x = B1f[e], y = B2f[e];
            m0 += u * u; m1 += x * x; m2 += y * y;
            m3 += u * x; m4 += u * y; m5 += x * y;
        }
        float xcm = sXc[f] * (1.0f / NROWS);
        float kf = w2[f] * xcm + b2[f];
        const float sF = 1.0f / FDIM;
        const float sQ = 1.0f / 32.0f;
        sCq[f * 6 + 0] = pk2(m0 * sQ, m1 * sQ);
        sCq[f * 6 + 1] = pk2(m2 * sQ, 2.f * m3 * sQ);
        sCq[f * 6 + 2] = pk2(2.f * m4 * sQ, 2.f * m5 * sQ);
        sCq[f * 6 + 3] = pk2(w1[f] * sF, b1[f] * sF);
        sCq[f * 6 + 4] = pk2(kf * sF, 0.f);
        sCq[f * 6 + 5] = 0ull;
    }
    #pragma unroll
    for (int idx = tid; idx < FDIM * NH1; idx += NTHR) {
        int f = idx >> 3, j = idx & 7;
        const float* lr  = L1w + j * (FDIM * EDIM) + f * EDIM;
        const float* Uf  = (const float*)&sS[f * 12];
        const float* B1f = Uf + 16;
        const float* B2f = Uf + 32;
        float P = 0, Q = 0, R = 0;
        #pragma unroll
        for (int e = 0; e < EDIM; e++) {
            float l = lr[e];
            P += Uf[e] * l; Q += B1f[e] * l; R += B2f[e] * l;
        }
        sMhF[f * 24 + j]      = P;
        sMhF[f * 24 + 8 + j]  = Q;
        sMhF[f * 24 + 16 + j] = R;
    }
    __syncthreads();

    // ================= Phase C: 4-quarter pipelined pass, 2 rows/thread =================
    u64 sE1[8], sE2[8], hv1[4], hv2[4];
    u64 ff1 = 0ull, ff2 = 0ull, q1 = 0ull, q2 = 0ull;
    #pragma unroll
    for (int g = 0; g < 8; g++) { sE1[g] = 0ull; sE2[g] = 0ull; }
    #pragma unroll
    for (int j = 0; j < 4; j++) { hv1[j] = 0ull; hv2[j] = 0ull; }

    const char* dynb = (const char*)dynsm;
    int rowoff1 = tid * 128;                     // row tid
    int rowoff2 = (tid + 256) * 128;             // row tid+256
    unsigned rx = (tid & 7) << 4;                // swizzle XOR (same for tid and tid+256)

    #pragma unroll 1
    for (int k = 0; k < 4; k++) {
        if (k < 3) asm volatile("cp.async.wait_group 1;" ::: "memory");
        else       asm volatile("cp.async.wait_group 0;" ::: "memory");
        __syncthreads();

        const char* b1p = dynb + (k & 1) * QBUF_BYTES + rowoff1;
        const char* b2p = dynb + (k & 1) * QBUF_BYTES + rowoff2;

        #pragma unroll
        for (int l = 0; l < 4; l++) {
            float4 xa1 = *(const float4*)(b1p + (((unsigned)(l << 4)) ^ rx));
            float4 xc1 = *(const float4*)(b1p + (((unsigned)((l + 4) << 4)) ^ rx));
            float4 xa2 = *(const float4*)(b2p + (((unsigned)(l << 4)) ^ rx));
            float4 xc2 = *(const float4*)(b2p + (((unsigned)((l + 4) << 4)) ^ rx));
            #pragma unroll
            for (int u = 0; u < 4; u++) {
                int f = k * 16 + l * 4 + u;
                float a1 = ((const float*)&xa1)[u];
                float c1v = ((const float*)&xc1)[u];
                float a2 = ((const float*)&xa2)[u];
                float c2v = ((const float*)&xc2)[u];
                float ac1 = a1 * c1v, ac2 = a2 * c2v;

                // ---- ff + quad per row (lane-paired) ----
                {
                    const ulonglong2* cqp = (const ulonglong2*)&sCq[f * 6];
                    ulonglong2 cq0 = cqp[0];       // (m0,m1) (m2,2m3)
                    ulonglong2 cq1 = cqp[1];       // (2m4,2m5) (w1,b1)
                    u64 kq = sCq[f * 6 + 4];       // (k,0)
                    {
                        u64 P1 = pk2(ac1, c1v);
                        q1 = fma2(mul2(P1, P1), cq0.x, q1);
                        q1 = fma2(mul2(pk2(a1, ac1), pk2(a1, c1v)), cq0.y, q1);
                        q1 = fma2(mul2(pk2(ac1, ac1), pk2(a1, 1.0f)), cq1.x, q1);
                        ff1 = fma2(P1, cq1.y, ff1);
                        ff1 = fma2(pk2(a1, a1), kq, ff1);
                    }
                    {
                        u64 P1 = pk2(ac2, c2v);
                        q2 = fma2(mul2(P1, P1), cq0.x, q2);
                        q2 = fma2(mul2(pk2(a2, ac2), pk2(a2, c2v)), cq0.y, q2);
                        q2 = fma2(mul2(pk2(ac2, ac2), pk2(a2, 1.0f)), cq1.x, q2);
                        ff2 = fma2(P1, cq1.y, ff2);
                        ff2 = fma2(pk2(a2, a2), kq, ff2);
                    }
                }

                u64 aa1 = pk2(a1, a1), cc1 = pk2(c1v, c1v), acac1 = pk2(ac1, ac1);
                u64 aa2 = pk2(a2, a2), cc2 = pk2(c2v, c2v), acac2 = pk2(ac2, ac2);

                // ---- s[e] matvec: 12 LDS.128 serve both rows ----
                const ulonglong2* sp = &sS[f * 12];
                #pragma unroll
                for (int g = 0; g < 4; g++) {
                    ulonglong2 uu  = sp[g];
                    ulonglong2 bb1 = sp[4 + g];
                    ulonglong2 bb2 = sp[8 + g];
                    sE1[2*g]   = fma2(uu.x,  acac1, sE1[2*g]);
                    sE1[2*g+1] = fma2(uu.y,  acac1, sE1[2*g+1]);
                    sE2[2*g]   = fma2(uu.x,  acac2, sE2[2*g]);
                    sE2[2*g+1] = fma2(uu.y,  acac2, sE2[2*g+1]);
                    sE1[2*g]   = fma2(bb1.x, cc1,   sE1[2*g]);
                    sE1[2*g+1] = fma2(bb1.y, cc1,   sE1[2*g+1]);
                    sE2[2*g]   = fma2(bb1.x, cc2,   sE2[2*g]);
                    sE2[2*g+1] = fma2(bb1.y, cc2,   sE2[2*g+1]);
                    sE1[2*g]   = fma2(bb2.x, aa1,   sE1[2*g]);
                    sE1[2*g+1] = fma2(bb2.y, aa1,   sE1[2*g+1]);
                    sE2[2*g]   = fma2(bb2.x, aa2,   sE2[2*g]);
                    sE2[2*g+1] = fma2(bb2.y, aa2,   sE2[2*g+1]);
                }
                // ---- h matvec: 6 LDS.128 serve both rows ----
                const ulonglong2* mh = (const ulonglong2*)&sMhF[f * 24];
                ulonglong2 P0 = mh[0], Pq = mh[1];
                ulonglong2 Q0 = mh[2], Qq = mh[3];
                ulonglong2 R0 = mh[4], Rq = mh[5];
                hv1[0] = fma2(P0.x, acac1, hv1[0]);
                hv1[1] = fma2(P0.y, acac1, hv1[1]);
                hv1[2] = fma2(Pq.x, acac1, hv1[2]);
                hv1[3] = fma2(Pq.y, acac1, hv1[3]);
                hv2[0] = fma2(P0.x, acac2, hv2[0]);
                hv2[1] = fma2(P0.y, acac2, hv2[1]);
                hv2[2] = fma2(Pq.x, acac2, hv2[2]);
                hv2[3] = fma2(Pq.y, acac2, hv2[3]);
                hv1[0] = fma2(Q0.x, cc1, hv1[0]);
                hv1[1] = fma2(Q0.y, cc1, hv1[1]);
                hv1[2] = fma2(Qq.x, cc1, hv1[2]);
                hv1[3] = fma2(Qq.y, cc1, hv1[3]);
                hv2[0] = fma2(Q0.x, cc2, hv2[0]);
                hv2[1] = fma2(Q0.y, cc2, hv2[1]);
                hv2[2] = fma2(Qq.x, cc2, hv2[2]);
                hv2[3] = fma2(Qq.y, cc2, hv2[3]);
                hv1[0] = fma2(R0.x, aa1, hv1[0]);
                hv1[1] = fma2(R0.y, aa1, hv1[1]);
                hv1[2] = fma2(Rq.x, aa1, hv1[2]);
                hv1[3] = fma2(Rq.y, aa1, hv1[3]);
                hv2[0] = fma2(R0.x, aa2, hv2[0]);
                hv2[1] = fma2(R0.y, aa2, hv2[1]);
                hv2[2] = fma2(Rq.x, aa2, hv2[2]);
                hv2[3] = fma2(Rq.y, aa2, hv2[3]);
            }
        }
        __syncthreads();              // buffer (k&1) fully consumed
        if (k < 2) issue_quarter(Xa, Xc, cta, k + 2, tid);
    }

    // ---- finalize fm parts ----
    float outv[2];
    {
        u64 ssv1 = 0ull, ssv2 = 0ull;
        #pragma unroll
        for (int e = 0; e < 8; e++) {
            ssv1 = fma2(sE1[e], sE1[e], ssv1);
            ssv2 = fma2(sE2[e], sE2[e], ssv2);
        }
        float2 sv1 = upk(ssv1), sv2 = upk(ssv2);
        float2 fp1 = upk(ff1), fp2 = upk(ff2);
        float2 qv1 = upk(q1), qv2 = upk(q2);
        outv[0] = (fp1.x + fp1.y) + (sv1.x + sv1.y) * (1.0f / 32.0f) - (qv1.x + qv1.y);
        outv[1] = (fp2.x + fp2.y) + (sv2.x + sv2.y) * (1.0f / 32.0f) - (qv2.x + qv2.y);
    }

    // ---- h with lin1_b ----
    float lb[8];
    {
        float4 lb0 = __ldg((const float4*)L1b);
        float4 lb1 = __ldg((const float4*)L1b + 1);
        lb[0]=lb0.x; lb[1]=lb0.y; lb[2]=lb0.z; lb[3]=lb0.w;
        lb[4]=lb1.x; lb[5]=lb1.y; lb[6]=lb1.z; lb[7]=lb1.w;
    }
    float hvf[2][8];
    #pragma unroll
    for (int j = 0; j < 4; j++) {
        float2 t1 = upk(hv1[j]);
        float2 t2 = upk(hv2[j]);
        hvf[0][2*j]   = t1.x + lb[2*j];
        hvf[0][2*j+1] = t1.y + lb[2*j+1];
        hvf[1][2*j]   = t2.x + lb[2*j];
        hvf[1][2*j+1] = t2.y + lb[2*j+1];
    }

    // ---- BN stats over both rows ----
    {
        float st[16];
        #pragma unroll
        for (int j = 0; j < NH1; j++) {
            st[j]     = hvf[0][j] + hvf[1][j];
            st[8 + j] = hvf[0][j] * hvf[0][j] + hvf[1][j] * hvf[1][j];
        }
        #pragma unroll
        for (int off = 16; off; off >>= 1) {
            #pragma unroll
            for (int j = 0; j < 16; j++)
                st[j] += __shfl_xor_sync(0xffffffffu, st[j], off);
        }
        if ((tid & 31) == 0) {
            #pragma unroll
            for (int j = 0; j < 16; j++) atomicAdd(&sStat[j], st[j]);
        }
        __syncthreads();
        if (tid < 16) atomicAdd(&g_hstat[tid], sStat[tid]);
    }
    grid_bar(&g_cnt1, &g_gen1);

    // ================= Phase D: BN finalize + tanh + lin2 + store =================
    if (tid < NH1) {
        float sh = __ldcg(&g_hstat[tid]);
        float sq = __ldcg(&g_hstat[NH1 + tid]);
        float mu  = sh * (1.0f / NROWS);
        float var = sq * (1.0f / NROWS) - mu * mu;
        float rs  = rsqrtf(var + BN_EPS);
        float al  = gam[tid] * rs;
        sFin[tid] = al;
        sFin[8 + tid] = bet[tid] - mu * al;
        float v = 0.f;
        #pragma unroll
        for (int j = 0; j < NH2; j++) v += L2w[j * NH1 + tid];
        sFin[16 + tid] = v * (1.0f / NH2);
    }
    if (tid == 0) {
        float cb = 0.f;
        #pragma unroll
        for (int j = 0; j < NH2; j++) cb += L2b[j];
        sFin[24] = cb * (1.0f / NH2);
    }
    __syncthreads();

    #pragma unroll
    for (int g = 0; g < 2; g++) {
        float acc = sFin[24];
        #pragma unroll
        for (int j = 0; j < NH1; j++)
            acc += sFin[16 + j] * ftanh(sFin[j] * hvf[g][j] + sFin[8 + j]);
        out[cta * ROWS_CTA + g * 256 + tid] = outv[g] + acc;
    }
}

extern "C" void kernel_launch(void* const* d_in, const int* in_sizes, int n_in,
                              void* d_out, int out_size)
{
    const float* Xa  = (const float*)d_in[0];
    const float* Xc  = (const float*)d_in[1];
    const float* w1  = (const float*)d_in[2];
    const float* b1  = (const float*)d_in[3];
    const float* w2  = (const float*)d_in[4];
    const float* b2  = (const float*)d_in[5];
    const float* W1  = (const float*)d_in[6];
    const float* B1  = (const float*)d_in[7];
    const float* W2  = (const float*)d_in[8];
    const float* B2  = (const float*)d_in[9];
    const float* L1w = (const float*)d_in[10];
    const float* L1b = (const float*)d_in[11];
    const float* g1  = (const float*)d_in[12];
    const float* be1 = (const float*)d_in[13];
    const float* L2w = (const float*)d_in[14];
    const float* L2b = (const float*)d_in[15];
    float* out = (float*)d_out;

    cudaFuncSetAttribute(k_all, cudaFuncAttributeMaxDynamicSharedMemorySize, DYN_BYTES);
    k_all<<<NCTA, NTHR, DYN_BYTES>>>(Xa, Xc, w1, b1, w2, b2, W1, B1, W2, B2,
                                     L1w, L1b, g1, be1, L2w, L2b, out);
}